// round 2
// baseline (speedup 1.0000x reference)
#include <cuda_runtime.h>
#include <math.h>

// Problem constants
#define GRID_SZ 14
#define L_SEQ   197           // 14*14 + 1
#define NH      12
#define DK      64
#define D_MODEL 768
#define BATCH   32
#define M_ROWS  (BATCH * L_SEQ)   // 6304
#define TOPK    32
#define N_ROWS_TOT (BATCH * NH * L_SEQ)  // 75648

// Scratch (device globals: no allocation allowed)
__device__ float g_Q[M_ROWS * D_MODEL];
__device__ float g_K[M_ROWS * D_MODEL];
__device__ float g_V[M_ROWS * D_MODEL];
__device__ float g_C[M_ROWS * D_MODEL];   // consensus (attention output before W_o)

// ---------------------------------------------------------------------------
// SGEMM:  C[M x 768] = A[M x 768] @ B[768 x 768] + bias
// Classic 128x128 tile, BK=8, 256 threads, 8x8 per-thread microtile.
// a_sel: 0 -> A_ext (x), 1 -> g_C
// c_sel: 0 -> g_Q, 1 -> g_K, 2 -> g_V, 3 -> C_ext (final out)
// ---------------------------------------------------------------------------
#define BM 128
#define BN 128
#define BK 8

__global__ __launch_bounds__(256) void sgemm_bias(
    const float* __restrict__ A_ext, int a_sel,
    const float* __restrict__ Bw, const float* __restrict__ bias,
    float* __restrict__ C_ext, int c_sel, int M)
{
    const float* A = (a_sel == 0) ? A_ext : g_C;
    float* C = (c_sel == 0) ? g_Q : (c_sel == 1) ? g_K : (c_sel == 2) ? g_V : C_ext;

    __shared__ float As[BK][BM];
    __shared__ float Bs[BK][BN];

    int bm = blockIdx.y, bn = blockIdx.x;
    int tid = threadIdx.x;
    int tx = tid & 15;       // 0..15  (N dir)
    int ty = tid >> 4;       // 0..15  (M dir)

    float acc[8][8];
#pragma unroll
    for (int i = 0; i < 8; i++)
#pragma unroll
        for (int j = 0; j < 8; j++) acc[i][j] = 0.f;

    int row0 = bm * BM;
    int col0 = bn * BN;

    // load mapping (float4 per thread per tile)
    int a_m = (tid * 4) / BK;   // 0..127
    int a_k = (tid * 4) % BK;   // 0 or 4
    int b_r = (tid * 4) / BN;   // 0..7
    int b_c = (tid * 4) % BN;   // 0..124 step 4

    for (int kt = 0; kt < D_MODEL; kt += BK) {
        float4 av = make_float4(0.f, 0.f, 0.f, 0.f);
        int gm = row0 + a_m;
        if (gm < M)
            av = *reinterpret_cast<const float4*>(&A[(size_t)gm * D_MODEL + kt + a_k]);
        As[a_k + 0][a_m] = av.x;
        As[a_k + 1][a_m] = av.y;
        As[a_k + 2][a_m] = av.z;
        As[a_k + 3][a_m] = av.w;

        float4 bv = *reinterpret_cast<const float4*>(&Bw[(size_t)(kt + b_r) * D_MODEL + col0 + b_c]);
        *reinterpret_cast<float4*>(&Bs[b_r][b_c]) = bv;

        __syncthreads();

#pragma unroll
        for (int k = 0; k < BK; k++) {
            float ra[8], rb[8];
#pragma unroll
            for (int i = 0; i < 4; i++) {
                ra[i]     = As[k][ty * 4 + i];
                ra[i + 4] = As[k][64 + ty * 4 + i];
            }
#pragma unroll
            for (int j = 0; j < 4; j++) {
                rb[j]     = Bs[k][tx * 4 + j];
                rb[j + 4] = Bs[k][64 + tx * 4 + j];
            }
#pragma unroll
            for (int i = 0; i < 8; i++)
#pragma unroll
                for (int j = 0; j < 8; j++)
                    acc[i][j] = fmaf(ra[i], rb[j], acc[i][j]);
        }
        __syncthreads();
    }

#pragma unroll
    for (int i = 0; i < 8; i++) {
        int m = row0 + ((i < 4) ? (ty * 4 + i) : (64 + ty * 4 + (i - 4)));
        if (m >= M) continue;
#pragma unroll
        for (int j = 0; j < 8; j++) {
            int n = col0 + ((j < 4) ? (tx * 4 + j) : (64 + tx * 4 + (j - 4)));
            C[(size_t)m * D_MODEL + n] = acc[i][j] + bias[n];
        }
    }
}

// ---------------------------------------------------------------------------
// Attention kernel: one warp per (b, h, i) row.
//   - i >= 1: <=26 valid columns (CLS + Chebyshev<=2 neighbors); top-32 is a
//     no-op, just softmax over valid set.
//   - i == 0: 197 valid columns; true top-32 (lowest-index tie-break like
//     jax.lax.top_k), then softmax over the 32.
// Writes dense weights + mask rows (zeros elsewhere) and consensus = w @ V.
// ---------------------------------------------------------------------------
__global__ __launch_bounds__(256) void attn_kernel(
    const float* __restrict__ log_sigma,
    float* __restrict__ w_out, float* __restrict__ m_out)
{
    __shared__ float q_sh[8][DK];

    int warp = threadIdx.x >> 5;
    int lane = threadIdx.x & 31;
    int rowid = blockIdx.x * 8 + warp;
    if (rowid >= N_ROWS_TOT) return;

    int b   = rowid / (NH * L_SEQ);
    int rem = rowid % (NH * L_SEQ);
    int h   = rem / L_SEQ;
    int i   = rem % L_SEQ;

    float inv = -0.5f * expf(-2.f * log_sigma[0]);   // -0.5 / sigma^2

    const float* qp = g_Q + (size_t)(b * L_SEQ + i) * D_MODEL + h * DK;
    float q0 = qp[lane];
    float q1 = qp[lane + 32];

    float myScore = 0.f;
    int   myCol   = -1;
    int   nj;

    if (i > 0) {
        // Build candidate list (same on all lanes): CLS + Chebyshev<=2 patches
        int p = i - 1, r = p / GRID_SZ, c = p % GRID_SZ;
        int cand[26];
        int n = 0;
        cand[n++] = 0;
        int r0 = (r - 2 < 0) ? 0 : r - 2;
        int r1 = (r + 2 > GRID_SZ - 1) ? GRID_SZ - 1 : r + 2;
        int c0 = (c - 2 < 0) ? 0 : c - 2;
        int c1 = (c + 2 > GRID_SZ - 1) ? GRID_SZ - 1 : c + 2;
        for (int rr = r0; rr <= r1; rr++)
            for (int cc = c0; cc <= c1; cc++)
                cand[n++] = 1 + rr * GRID_SZ + cc;
        nj = n;

        for (int t = 0; t < n; t++) {
            int j = cand[t];
            const float* kp = g_K + (size_t)(b * L_SEQ + j) * D_MODEL + h * DK;
            float d0 = q0 - kp[lane];
            float d1 = q1 - kp[lane + 32];
            float s = d0 * d0 + d1 * d1;
#pragma unroll
            for (int o = 16; o > 0; o >>= 1)
                s += __shfl_xor_sync(0xffffffffu, s, o);
            if (lane == t) { myScore = inv * s; myCol = j; }
        }
    } else {
        // CLS row: 197 candidates, true top-32.
        q_sh[warp][lane]      = q0;
        q_sh[warp][lane + 32] = q1;
        __syncwarp();

        float sc[7];
#pragma unroll
        for (int s = 0; s < 7; s++) {
            int j = s * 32 + lane;
            if (j < L_SEQ) {
                const float* kp = g_K + (size_t)(b * L_SEQ + j) * D_MODEL + h * DK;
                float acc = 0.f;
#pragma unroll
                for (int d = 0; d < DK; d++) {
                    float df = q_sh[warp][d] - kp[d];
                    acc += df * df;
                }
                sc[s] = inv * acc;
            } else {
                sc[s] = -INFINITY;
            }
        }

        unsigned used = 0;
        for (int t = 0; t < TOPK; t++) {
            float bv = -INFINITY;
            int   bj = 0x7fffffff;
#pragma unroll
            for (int s = 0; s < 7; s++) {
                if (!((used >> s) & 1u)) {
                    int j = s * 32 + lane;
                    if (sc[s] > bv || (sc[s] == bv && j < bj)) { bv = sc[s]; bj = j; }
                }
            }
#pragma unroll
            for (int o = 16; o > 0; o >>= 1) {
                float ov = __shfl_xor_sync(0xffffffffu, bv, o);
                int   oj = __shfl_xor_sync(0xffffffffu, bj, o);
                if (ov > bv || (ov == bv && oj < bj)) { bv = ov; bj = oj; }
            }
            if (lane == (bj & 31)) used |= 1u << (bj >> 5);  // mark winner consumed
            if (lane == t) { myScore = bv; myCol = bj; }
        }
        nj = TOPK;
    }

    // Softmax over lanes [0, nj)
    bool  act = lane < nj;
    float v   = act ? myScore : -INFINITY;
    float mx  = v;
#pragma unroll
    for (int o = 16; o > 0; o >>= 1)
        mx = fmaxf(mx, __shfl_xor_sync(0xffffffffu, mx, o));
    float e = act ? expf(myScore - mx) : 0.f;
    float se = e;
#pragma unroll
    for (int o = 16; o > 0; o >>= 1)
        se += __shfl_xor_sync(0xffffffffu, se, o);
    float w = e / se;

    // Write dense weights + mask rows
    float* wrow = w_out + (size_t)rowid * L_SEQ;
    float* mrow = m_out + (size_t)rowid * L_SEQ;
    for (int t = lane; t < L_SEQ; t += 32) { wrow[t] = 0.f; mrow[t] = 0.f; }
    __syncwarp();
    if (act) {
        wrow[myCol] = w;
        mrow[myCol] = (w > 1e-6f) ? 1.f : 0.f;
    }

    // Consensus: sum_j w_j * V[b,h,j,:]
    float a0 = 0.f, a1 = 0.f;
    for (int t = 0; t < nj; t++) {
        float wv  = __shfl_sync(0xffffffffu, w, t);
        int   col = __shfl_sync(0xffffffffu, myCol, t);
        const float* vp = g_V + (size_t)(b * L_SEQ + col) * D_MODEL + h * DK;
        a0 = fmaf(wv, vp[lane], a0);
        a1 = fmaf(wv, vp[lane + 32], a1);
    }
    float* cp = g_C + (size_t)(b * L_SEQ + i) * D_MODEL + h * DK;
    cp[lane]      = a0;
    cp[lane + 32] = a1;
}

// ---------------------------------------------------------------------------
extern "C" void kernel_launch(void* const* d_in, const int* in_sizes, int n_in,
                              void* d_out, int out_size)
{
    const float* x  = (const float*)d_in[0];
    const float* Wq = (const float*)d_in[1];
    const float* bq = (const float*)d_in[2];
    const float* Wk = (const float*)d_in[3];
    const float* bk = (const float*)d_in[4];
    const float* Wv = (const float*)d_in[5];
    const float* bv = (const float*)d_in[6];
    const float* Wo = (const float*)d_in[7];
    const float* bo = (const float*)d_in[8];
    const float* ls = (const float*)d_in[9];

    float* out   = (float*)d_out;                                    // (B, L, D)
    float* w_out = out + (size_t)M_ROWS * D_MODEL;                   // (B, H, L, L)
    float* m_out = w_out + (size_t)BATCH * NH * L_SEQ * L_SEQ;       // (B, H, L, L)

    dim3 ggrid(D_MODEL / BN, (M_ROWS + BM - 1) / BM);   // (6, 50)
    dim3 gblk(256);

    // QKV projections
    sgemm_bias<<<ggrid, gblk>>>(x, 0, Wq, bq, nullptr, 0, M_ROWS);
    sgemm_bias<<<ggrid, gblk>>>(x, 0, Wk, bk, nullptr, 1, M_ROWS);
    sgemm_bias<<<ggrid, gblk>>>(x, 0, Wv, bv, nullptr, 2, M_ROWS);

    // Attention (scores + topk + softmax + weights/mask + consensus)
    int nblk = (N_ROWS_TOT + 7) / 8;
    attn_kernel<<<nblk, 256>>>(ls, w_out, m_out);

    // Output projection
    sgemm_bias<<<ggrid, gblk>>>(nullptr, 1, Wo, bo, out, 3, M_ROWS);
}